// round 10
// baseline (speedup 1.0000x reference)
#include <cuda_runtime.h>
#include <cuda_bf16.h>
#include <math.h>
#include <stdint.h>

// Problem constants
#define BB 2
#define SS 2048
#define DD 1024
#define HH 16
#define RR 64
#define NN 32
#define RKK 128
#define DHH 64
#define BSZ (BB*SS)
#define NR (NN*RR)           // 2048
#define NRK (NN*RKK)         // 4096
#define LN_EPS 1e-5f

typedef __nv_bfloat16 bf16;
typedef uint8_t fp8;

// quantization scales (powers of 2)
#define SQ_ACT  16.0f
#define SQ_W    512.0f
#define SQ_T    32.0f
#define SQ_ATTN 64.0f
#define INV_FEAT (1.0f/(SQ_ACT*SQ_W))
#define INV_REST (1.0f/(SQ_T*SQ_W))
#define INV_WO   (1.0f/(SQ_ATTN*SQ_W))

// ---------------- scratch ----------------------------------------------------
__device__ fp8   g_BqkvT[(size_t)2*NR*DD];
__device__ fp8   g_BknT[(size_t)NRK*DD];
__device__ fp8   g_WOb[(size_t)DD*DD];
__device__ fp8   g_rqkT[(size_t)DD*NR];
__device__ fp8   g_rvT [(size_t)DD*NR];
__device__ fp8   g_rknT[(size_t)DD*NRK];
__device__ fp8   g_nx [BSZ*DD];
__device__ bf16  g_allh[(size_t)BSZ*4096];
__device__ fp8   g_Tqk[(size_t)2*BSZ*NR];
__device__ fp8   g_Tv [(size_t)BSZ*NR];
__device__ fp8   g_Tkn[(size_t)BSZ*NRK];
__device__ bf16  g_QKb[(size_t)2*BSZ*DD];
__device__ bf16  g_Vb[BSZ*DD];
__device__ fp8   g_attn[BSZ*DD];
__device__ float g_x1[BSZ*DD];

// ---------------- helpers ----------------------------------------------------
__device__ __forceinline__ uint32_t smem_u32(const void* p) {
    return (uint32_t)__cvta_generic_to_shared(p);
}
__device__ __forceinline__ void cp16(uint32_t saddr, const void* gaddr) {
    asm volatile("cp.async.cg.shared.global [%0], [%1], 16;\n" :: "r"(saddr), "l"(gaddr));
}
__device__ __forceinline__ void cp_commit() { asm volatile("cp.async.commit_group;\n"); }
template<int N> __device__ __forceinline__ void cp_wait() {
    asm volatile("cp.async.wait_group %0;\n" :: "n"(N));
}
__device__ __forceinline__ void ldsm_x4(uint32_t& r0, uint32_t& r1, uint32_t& r2, uint32_t& r3, uint32_t addr) {
    asm volatile("ldmatrix.sync.aligned.m8n8.x4.shared.b16 {%0,%1,%2,%3}, [%4];\n"
                 : "=r"(r0), "=r"(r1), "=r"(r2), "=r"(r3) : "r"(addr));
}
__device__ __forceinline__ void ldsm_x4_t(uint32_t& r0, uint32_t& r1, uint32_t& r2, uint32_t& r3, uint32_t addr) {
    asm volatile("ldmatrix.sync.aligned.m8n8.x4.trans.shared.b16 {%0,%1,%2,%3}, [%4];\n"
                 : "=r"(r0), "=r"(r1), "=r"(r2), "=r"(r3) : "r"(addr));
}
__device__ __forceinline__ void mma16816(float* d, const uint32_t* a, const uint32_t* b) {
    asm volatile("mma.sync.aligned.m16n8k16.row.col.f32.bf16.bf16.f32 "
                 "{%0,%1,%2,%3}, {%4,%5,%6,%7}, {%8,%9}, {%0,%1,%2,%3};\n"
                 : "+f"(d[0]), "+f"(d[1]), "+f"(d[2]), "+f"(d[3])
                 : "r"(a[0]), "r"(a[1]), "r"(a[2]), "r"(a[3]), "r"(b[0]), "r"(b[1]));
}
__device__ __forceinline__ void mma16832fp8(float* d, const uint32_t* a, const uint32_t* b) {
    asm volatile("mma.sync.aligned.m16n8k32.row.col.f32.e4m3.e4m3.f32 "
                 "{%0,%1,%2,%3}, {%4,%5,%6,%7}, {%8,%9}, {%0,%1,%2,%3};\n"
                 : "+f"(d[0]), "+f"(d[1]), "+f"(d[2]), "+f"(d[3])
                 : "r"(a[0]), "r"(a[1]), "r"(a[2]), "r"(a[3]), "r"(b[0]), "r"(b[1]));
}
__device__ __forceinline__ uint32_t pack_bf16(float x, float y) {
    __nv_bfloat162 t = __floats2bfloat162_rn(x, y);
    return *(uint32_t*)&t;
}
__device__ __forceinline__ uint16_t pack_fp8x2(float lo, float hi) {
    uint16_t v;
    asm("cvt.rn.satfinite.e4m3x2.f32 %0, %1, %2;" : "=h"(v) : "f"(hi), "f"(lo));
    return v;
}
__device__ __forceinline__ fp8 cvt_fp8(float x) {
    uint16_t v;
    asm("cvt.rn.satfinite.e4m3x2.f32 %0, %1, %2;" : "=h"(v) : "f"(0.f), "f"(x));
    return (fp8)(v & 0xFF);
}

// ================== FP8 tensor-core GEMM =====================================
// C[M,Nc] = invs*(A[M,K] @ Bt[Nc,K]^T)(+Res). 128x128 CTA, TK=64B,
// 4-stage cp.async ring, 3 tiles in flight, one __syncthreads per K-iter.
#define QSTR 80
#define QSTG (128*QSTR)            // bytes per tile buffer
#define QSMEM (4*2*QSTG)           // 81920 bytes

template<typename OutT>
__global__ __launch_bounds__(256, 2)
void qgemm_kernel(const fp8* __restrict__ A, const fp8* __restrict__ Bt,
                  OutT* __restrict__ C, const float* __restrict__ Res,
                  float invs, int M, int Nc, int K) {
    extern __shared__ fp8 qs[];
    fp8* As = qs;                  // [4][128][QSTR]
    fp8* Bs = qs + 4*QSTG;
    int tid = threadIdx.x;
    int lane = tid & 31;
    int warp = tid >> 5;
    int warp_m = warp & 1;
    int warp_n = warp >> 1;

    const fp8* Ab = A + (size_t)blockIdx.y * 128 * K;
    const fp8* Bb = Bt + (size_t)blockIdx.x * 128 * K;

    float acc[4][4][4];
    #pragma unroll
    for (int i = 0; i < 4; i++)
        #pragma unroll
        for (int j = 0; j < 4; j++)
            #pragma unroll
            for (int v = 0; v < 4; v++) acc[i][j][v] = 0.f;

    int ldrow = tid >> 1;
    int ldc   = (tid & 1) * 32;
    int KT = K >> 6;

    // prologue: stages 0,1,2
    #pragma unroll
    for (int p = 0; p < 3; p++) {
        int k0 = p * 64;
        uint32_t sa = smem_u32(As + p*QSTG + ldrow*QSTR + ldc);
        uint32_t sb = smem_u32(Bs + p*QSTG + ldrow*QSTR + ldc);
        cp16(sa,      Ab + (size_t)ldrow * K + k0 + ldc);
        cp16(sa + 16, Ab + (size_t)ldrow * K + k0 + ldc + 16);
        cp16(sb,      Bb + (size_t)ldrow * K + k0 + ldc);
        cp16(sb + 16, Bb + (size_t)ldrow * K + k0 + ldc + 16);
        cp_commit();
    }

    for (int kt = 0; kt < KT; kt++) {
        int st = kt & 3;
        cp_wait<2>();
        __syncthreads();
        // issue loads for kt+3 (stage computed at kt-1; all threads past sync)
        if (kt + 3 < KT) {
            int ps = (kt + 3) & 3;
            int k0 = (kt + 3) * 64;
            uint32_t sa = smem_u32(As + ps*QSTG + ldrow*QSTR + ldc);
            uint32_t sb = smem_u32(Bs + ps*QSTG + ldrow*QSTR + ldc);
            cp16(sa,      Ab + (size_t)ldrow * K + k0 + ldc);
            cp16(sa + 16, Ab + (size_t)ldrow * K + k0 + ldc + 16);
            cp16(sb,      Bb + (size_t)ldrow * K + k0 + ldc);
            cp16(sb + 16, Bb + (size_t)ldrow * K + k0 + ldc + 16);
        }
        cp_commit();   // always commit: keeps pending-group arithmetic fixed
        fp8* Ast = As + st*QSTG;
        fp8* Bst = Bs + st*QSTG;
        #pragma unroll
        for (int kk = 0; kk < 64; kk += 32) {
            uint32_t af[4][4];
            #pragma unroll
            for (int i = 0; i < 4; i++) {
                int row = warp_m * 64 + i * 16 + (lane & 15);
                int col = kk + (lane >> 4) * 16;
                ldsm_x4(af[i][0], af[i][1], af[i][2], af[i][3], smem_u32(Ast + row*QSTR + col));
            }
            uint32_t bfr[4][2];
            #pragma unroll
            for (int np = 0; np < 2; np++) {
                int row = warp_n * 32 + np * 16 + (lane & 7) + ((lane & 16) ? 8 : 0);
                int col = kk + ((lane & 8) ? 16 : 0);
                uint32_t r0, r1, r2, r3;
                ldsm_x4(r0, r1, r2, r3, smem_u32(Bst + row*QSTR + col));
                bfr[np*2][0] = r0; bfr[np*2][1] = r1;
                bfr[np*2+1][0] = r2; bfr[np*2+1][1] = r3;
            }
            #pragma unroll
            for (int i = 0; i < 4; i++)
                #pragma unroll
                for (int j = 0; j < 4; j++)
                    mma16832fp8(acc[i][j], af[i], bfr[j]);
        }
    }

    size_t blockRow = (size_t)blockIdx.y * 128;
    size_t blockCol = (size_t)blockIdx.x * 128;
    #pragma unroll
    for (int i = 0; i < 4; i++) {
        size_t r0 = blockRow + warp_m * 64 + i * 16 + (lane >> 2);
        #pragma unroll
        for (int j = 0; j < 4; j++) {
            size_t c0 = blockCol + warp_n * 32 + j * 8 + (lane & 3) * 2;
            float a0 = acc[i][j][0] * invs, a1 = acc[i][j][1] * invs;
            float a2 = acc[i][j][2] * invs, a3 = acc[i][j][3] * invs;
            if constexpr (sizeof(OutT) == 4) {
                float2 v0 = make_float2(a0, a1);
                float2 v1 = make_float2(a2, a3);
                if (Res) {
                    const float2 q0 = *(const float2*)(Res + r0 * Nc + c0);
                    const float2 q1 = *(const float2*)(Res + (r0 + 8) * Nc + c0);
                    v0.x += q0.x; v0.y += q0.y; v1.x += q1.x; v1.y += q1.y;
                }
                *(float2*)((float*)C + r0 * Nc + c0) = v0;
                *(float2*)((float*)C + (r0 + 8) * Nc + c0) = v1;
            } else {
                *(uint32_t*)((bf16*)C + r0 * Nc + c0)       = pack_bf16(a0, a1);
                *(uint32_t*)((bf16*)C + (r0 + 8) * Nc + c0) = pack_bf16(a2, a3);
            }
        }
    }
}

// ---------------- batched pack f[n,d,r] -> fp8 B^T ---------------------------
// z=0: f_qk -> BqkvT[0],  z=1: f_v -> BqkvT[NR],  z=2: f_know -> BknT
__global__ void pack_fT3_kernel(const float* __restrict__ f_qk, const float* __restrict__ f_v,
                                const float* __restrict__ f_know,
                                fp8* __restrict__ BqkvT, fp8* __restrict__ BknT) {
    int z = blockIdx.z;
    const float* in = (z == 0) ? f_qk : (z == 1) ? f_v : f_know;
    int Rr = (z == 2) ? RKK : RR;
    fp8* out = (z == 2) ? BknT : (BqkvT + (z == 1 ? (size_t)NR * DD : 0));
    int total = DD * NN * Rr;
    int idx = blockIdx.x * blockDim.x + threadIdx.x;
    if (idx >= total) return;
    int d = idx & (DD - 1);
    int col = idx >> 10;
    int n = col / Rr;
    int r = col - n * Rr;
    out[(size_t)col * DD + d] = cvt_fp8(in[((size_t)n * DD + d) * Rr + r] * SQ_W);
}

__global__ void cvt_fp8_kernel(const float* __restrict__ in, fp8* __restrict__ out, int n) {
    int i = blockIdx.x * blockDim.x + threadIdx.x;
    if (i < n) out[i] = cvt_fp8(in[i] * SQ_W);
}

// batched transpose+fp8: z selects (r_qk, r_v, r_know); out [cols, rows]
__global__ void transpose_q3_kernel(const float* __restrict__ r_qk, const float* __restrict__ r_v,
                                    const float* __restrict__ r_know,
                                    fp8* __restrict__ rqkT, fp8* __restrict__ rvT,
                                    fp8* __restrict__ rknT) {
    int z = blockIdx.z;
    const float* in = (z == 0) ? r_qk : (z == 1) ? r_v : r_know;
    fp8* out = (z == 0) ? rqkT : (z == 1) ? rvT : rknT;
    int rows = (z == 2) ? NRK : NR;
    if (blockIdx.y * 32 >= rows) return;
    __shared__ float tile[32][33];
    int x = blockIdx.x * 32 + threadIdx.x;
    int y = blockIdx.y * 32 + threadIdx.y;
    #pragma unroll
    for (int i = 0; i < 32; i += 8)
        tile[threadIdx.y + i][threadIdx.x] = in[(size_t)(y + i) * DD + x];
    __syncthreads();
    x = blockIdx.y * 32 + threadIdx.x;
    y = blockIdx.x * 32 + threadIdx.y;
    #pragma unroll
    for (int i = 0; i < 32; i += 8)
        out[(size_t)(y + i) * rows + x] = cvt_fp8(tile[threadIdx.x][threadIdx.y + i] * SQ_W);
}

// ---------------- LayerNorm (fp8 out) ----------------------------------------
__global__ void ln_kernel(const float* __restrict__ x, const float* __restrict__ g,
                          const float* __restrict__ b, fp8* __restrict__ out) {
    int row = blockIdx.x;
    const float* xr = x + (size_t)row * DD;
    int c = threadIdx.x * 4;
    float4 xv = *(const float4*)(xr + c);
    float s  = xv.x + xv.y + xv.z + xv.w;
    float sq = xv.x*xv.x + xv.y*xv.y + xv.z*xv.z + xv.w*xv.w;
    #pragma unroll
    for (int o = 16; o > 0; o >>= 1) {
        s  += __shfl_xor_sync(0xffffffffu, s,  o);
        sq += __shfl_xor_sync(0xffffffffu, sq, o);
    }
    __shared__ float ss[8], ssq[8];
    __shared__ float mean_s, rstd_s;
    int wid = threadIdx.x >> 5, lid = threadIdx.x & 31;
    if (lid == 0) { ss[wid] = s; ssq[wid] = sq; }
    __syncthreads();
    if (threadIdx.x == 0) {
        float S = 0.f, SQ = 0.f;
        #pragma unroll
        for (int i = 0; i < 8; i++) { S += ss[i]; SQ += ssq[i]; }
        float mu  = S * (1.f / DD);
        float var = SQ * (1.f / DD) - mu * mu;
        mean_s = mu;
        rstd_s = rsqrtf(var + LN_EPS);
    }
    __syncthreads();
    float mu = mean_s, rs = rstd_s;
    float4 gv = *(const float4*)(g + c);
    float4 bv = *(const float4*)(b + c);
    float o0 = (gv.x * (xv.x - mu) * rs + bv.x) * SQ_ACT;
    float o1 = (gv.y * (xv.y - mu) * rs + bv.y) * SQ_ACT;
    float o2 = (gv.z * (xv.z - mu) * rs + bv.z) * SQ_ACT;
    float o3 = (gv.w * (xv.w - mu) * rs + bv.w) * SQ_ACT;
    uint32_t pk = (uint32_t)pack_fp8x2(o0, o1) | ((uint32_t)pack_fp8x2(o2, o3) << 16);
    *(uint32_t*)(out + (size_t)row * DD + c) = pk;
}

// ---------------- fused combine + buildT (bf16 allh in, fp8 T out) -----------
__global__ void combineT_kernel(const bf16* __restrict__ allh, int stride,
                                const float* __restrict__ wf1, const float* __restrict__ wf2,
                                const float* __restrict__ wr1, const float* __restrict__ wr2,
                                fp8* __restrict__ T1, fp8* __restrict__ T2, int Rr) {
    int bs = blockIdx.x;
    int tid = threadIdx.x;
    __shared__ float h1s[RKK], h2s[RKK];
    __shared__ float wf1s[NN], wf2s[NN], wr1s[NN], wr2s[NN];
    if (tid < NN) {
        wf1s[tid] = wf1[(size_t)bs * NN + tid];
        wr1s[tid] = wr1[(size_t)bs * NN + tid] * SQ_T;
        if (wf2) { wf2s[tid] = wf2[(size_t)bs * NN + tid]; wr2s[tid] = wr2[(size_t)bs * NN + tid] * SQ_T; }
    }
    __syncthreads();
    if (tid < Rr) {
        const bf16* rowp = allh + (size_t)bs * stride;
        float a1 = 0.f, a2 = 0.f;
        #pragma unroll 8
        for (int n = 0; n < NN; n++) {
            float v = __bfloat162float(rowp[n * Rr + tid]);
            a1 += wf1s[n] * v;
            if (wf2) a2 += wf2s[n] * v;
        }
        h1s[tid] = a1;
        if (wf2) h2s[tid] = a2;
    }
    __syncthreads();
    int total = NN * Rr;
    fp8* T1row = T1 + (size_t)bs * total;
    fp8* T2row = wf2 ? (T2 + (size_t)bs * total) : nullptr;
    for (int i = tid; i < total; i += 256) {
        int n = i / Rr;
        int r = i - n * Rr;
        T1row[i] = cvt_fp8(wr1s[n] * h1s[r]);
        if (wf2) T2row[i] = cvt_fp8(wr2s[n] * h2s[r]);
    }
}

// ================= bf16 mma.sync flash attention (fp8 output) ================
#define KSTR 72
#define SC2 (0.125f * 1.44269504f)

__global__ __launch_bounds__(128)
void attn_mma_kernel(const bf16* __restrict__ Q, const bf16* __restrict__ K,
                     const bf16* __restrict__ V, fp8* __restrict__ O) {
    __shared__ bf16 Qs[64][KSTR];
    __shared__ bf16 Ks[2][64][KSTR];
    __shared__ bf16 Vs[2][64][KSTR];

    int qt = gridDim.x - 1 - blockIdx.x;
    int h = blockIdx.y, b = blockIdx.z;
    int tid = threadIdx.x;
    int lane = tid & 31, w = tid >> 5;
    size_t headoff = (size_t)h * DHH;

    const bf16* Qbase = Q + ((size_t)(b * SS + qt * 64)) * DD + headoff;
    const bf16* Kbase = K + ((size_t)b * SS) * DD + headoff;
    const bf16* Vbase = V + ((size_t)b * SS) * DD + headoff;

    #pragma unroll
    for (int i = 0; i < 4; i++) {
        int c = tid + i * 128;
        int row = c >> 3, off = (c & 7) * 8;
        cp16(smem_u32(&Qs[row][off]), Qbase + (size_t)row * DD + off);
    }
    cp_commit();
    #pragma unroll
    for (int i = 0; i < 4; i++) {
        int c = tid + i * 128;
        int row = c >> 3, off = (c & 7) * 8;
        cp16(smem_u32(&Ks[0][row][off]), Kbase + (size_t)row * DD + off);
        cp16(smem_u32(&Vs[0][row][off]), Vbase + (size_t)row * DD + off);
    }
    cp_commit();

    cp_wait<1>();
    __syncthreads();
    uint32_t aq[4][4];
    #pragma unroll
    for (int kc = 0; kc < 4; kc++) {
        int row = w * 16 + (lane & 15);
        int col = kc * 16 + (lane >> 4) * 8;
        ldsm_x4(aq[kc][0], aq[kc][1], aq[kc][2], aq[kc][3], smem_u32(&Qs[row][col]));
    }

    float acc_o[8][4];
    #pragma unroll
    for (int nt = 0; nt < 8; nt++)
        #pragma unroll
        for (int v = 0; v < 4; v++) acc_o[nt][v] = 0.f;
    float m[2] = {-INFINITY, -INFINITY};
    float l[2] = {0.f, 0.f};

    int ntiles = qt + 1;
    for (int j = 0; j < ntiles; j++) {
        int st = j & 1;
        if (j + 1 < ntiles) {
            const bf16* kb = Kbase + (size_t)(j + 1) * 64 * DD;
            const bf16* vb = Vbase + (size_t)(j + 1) * 64 * DD;
            #pragma unroll
            for (int i = 0; i < 4; i++) {
                int c = tid + i * 128;
                int row = c >> 3, off = (c & 7) * 8;
                cp16(smem_u32(&Ks[st ^ 1][row][off]), kb + (size_t)row * DD + off);
                cp16(smem_u32(&Vs[st ^ 1][row][off]), vb + (size_t)row * DD + off);
            }
            cp_commit();
            cp_wait<1>();
        } else {
            cp_wait<0>();
        }
        __syncthreads();

        float s[8][4];
        #pragma unroll
        for (int nt = 0; nt < 8; nt++)
            #pragma unroll
            for (int v = 0; v < 4; v++) s[nt][v] = 0.f;
        #pragma unroll
        for (int kc = 0; kc < 4; kc++) {
            uint32_t bk[8][2];
            #pragma unroll
            for (int np = 0; np < 4; np++) {
                int row = np * 16 + (lane & 7) + ((lane & 16) ? 8 : 0);
                int colk = kc * 16 + ((lane & 8) ? 8 : 0);
                uint32_t r0, r1, r2, r3;
                ldsm_x4(r0, r1, r2, r3, smem_u32(&Ks[st][row][colk]));
                bk[np*2][0] = r0; bk[np*2][1] = r1;
                bk[np*2+1][0] = r2; bk[np*2+1][1] = r3;
            }
            #pragma unroll
            for (int nt = 0; nt < 8; nt++)
                mma16816(s[nt], aq[kc], bk[nt]);
        }

        if (j == qt) {
            int r0 = w * 16 + (lane >> 2);
            int cb = (lane & 3) * 2;
            #pragma unroll
            for (int nt = 0; nt < 8; nt++) {
                #pragma unroll
                for (int v = 0; v < 4; v++) {
                    int col = nt * 8 + cb + (v & 1);
                    int row = r0 + ((v & 2) ? 8 : 0);
                    if (col > row) s[nt][v] = -INFINITY;
                }
            }
        }

        #pragma unroll
        for (int rh = 0; rh < 2; rh++) {
            float mt = -INFINITY;
            #pragma unroll
            for (int nt = 0; nt < 8; nt++)
                mt = fmaxf(mt, fmaxf(s[nt][rh*2], s[nt][rh*2+1]));
            mt = fmaxf(mt, __shfl_xor_sync(0xffffffffu, mt, 1));
            mt = fmaxf(mt, __shfl_xor_sync(0xffffffffu, mt, 2));
            float mn = fmaxf(m[rh], mt);
            float corr = exp2f((m[rh] - mn) * SC2);
            m[rh] = mn;
            float ls = 0.f;
            #pragma unroll
            for (int nt = 0; nt < 8; nt++) {
                float p0 = exp2f((s[nt][rh*2]   - mn) * SC2);
                float p1 = exp2f((s[nt][rh*2+1] - mn) * SC2);
                s[nt][rh*2] = p0; s[nt][rh*2+1] = p1;
                ls += p0 + p1;
            }
            ls += __shfl_xor_sync(0xffffffffu, ls, 1);
            ls += __shfl_xor_sync(0xffffffffu, ls, 2);
            l[rh] = l[rh] * corr + ls;
            #pragma unroll
            for (int nt = 0; nt < 8; nt++) {
                acc_o[nt][rh*2]   *= corr;
                acc_o[nt][rh*2+1] *= corr;
            }
        }

        #pragma unroll
        for (int kc = 0; kc < 4; kc++) {
            uint32_t pa[4];
            pa[0] = pack_bf16(s[2*kc][0],   s[2*kc][1]);
            pa[1] = pack_bf16(s[2*kc][2],   s[2*kc][3]);
            pa[2] = pack_bf16(s[2*kc+1][0], s[2*kc+1][1]);
            pa[3] = pack_bf16(s[2*kc+1][2], s[2*kc+1][3]);
            uint32_t bv[8][2];
            #pragma unroll
            for (int np = 0; np < 4; np++) {
                int kr = kc * 16 + (lane & 7) + ((lane & 16) ? 8 : 0);
                int col = np * 16 + ((lane & 8) ? 8 : 0);
                uint32_t r0, r1, r2, r3;
                ldsm_x4_t(r0, r1, r2, r3, smem_u32(&Vs[st][kr][col]));
                bv[np*2][0] = r0; bv[np*2+1][0] = r1;
                bv[np*2][1] = r2; bv[np*2+1][1] = r3;
            }
            #pragma unroll
            for (int nt = 0; nt < 8; nt++)
                mma16816(acc_o[nt], pa, bv[nt]);
        }
        __syncthreads();
    }

    float inv0 = SQ_ATTN / l[0];
    float inv1 = SQ_ATTN / l[1];
    int row0 = qt * 64 + w * 16 + (lane >> 2);
    fp8* Ob = O + ((size_t)b * SS) * DD + headoff;
    #pragma unroll
    for (int nt = 0; nt < 8; nt++) {
        int col = nt * 8 + (lane & 3) * 2;
        *(uint16_t*)(Ob + (size_t)row0 * DD + col)       = pack_fp8x2(acc_o[nt][0] * inv0, acc_o[nt][1] * inv0);
        *(uint16_t*)(Ob + (size_t)(row0 + 8) * DD + col) = pack_fp8x2(acc_o[nt][2] * inv1, acc_o[nt][3] * inv1);
    }
}

// ---------------- launch -----------------------------------------------------
extern "C" void kernel_launch(void* const* d_in, const int* in_sizes, int n_in,
                              void* d_out, int out_size) {
    const float* x       = (const float*)d_in[0];
    const float* f_qk    = (const float*)d_in[1];
    const float* f_v     = (const float*)d_in[2];
    const float* r_qk    = (const float*)d_in[3];
    const float* r_v     = (const float*)d_in[4];
    const float* f_know  = (const float*)d_in[5];
    const float* r_know  = (const float*)d_in[6];
    const float* W_O     = (const float*)d_in[7];
    const float* gamma1  = (const float*)d_in[8];
    const float* beta1   = (const float*)d_in[9];
    const float* gamma2  = (const float*)d_in[10];
    const float* beta2   = (const float*)d_in[11];
    const float* w_fq    = (const float*)d_in[12];
    const float* w_fk    = (const float*)d_in[13];
    const float* w_fv    = (const float*)d_in[14];
    const float* w_rq    = (const float*)d_in[15];
    const float* w_rk    = (const float*)d_in[16];
    const float* w_rv    = (const float*)d_in[17];
    const float* w_know_f= (const float*)d_in[18];
    const float* w_know_r= (const float*)d_in[19];
    float* out = (float*)d_out;

    fp8 *BqkvT, *BknT, *WOb, *rqkT, *rvT, *rknT, *nx, *Tqk, *Tv, *Tkn, *attn;
    bf16 *QKb, *Vb, *allh;
    float *x1;
    cudaGetSymbolAddress((void**)&BqkvT, g_BqkvT);
    cudaGetSymbolAddress((void**)&BknT, g_BknT);
    cudaGetSymbolAddress((void**)&WOb, g_WOb);
    cudaGetSymbolAddress((void**)&rqkT, g_rqkT);
    cudaGetSymbolAddress((void**)&rvT,  g_rvT);
    cudaGetSymbolAddress((void**)&rknT, g_rknT);
    cudaGetSymbolAddress((void**)&nx,  g_nx);
    cudaGetSymbolAddress((void**)&allh, g_allh);
    cudaGetSymbolAddress((void**)&Tqk, g_Tqk);
    cudaGetSymbolAddress((void**)&Tv,  g_Tv);
    cudaGetSymbolAddress((void**)&Tkn, g_Tkn);
    cudaGetSymbolAddress((void**)&QKb, g_QKb);
    cudaGetSymbolAddress((void**)&Vb,  g_Vb);
    cudaGetSymbolAddress((void**)&attn, g_attn);
    cudaGetSymbolAddress((void**)&x1, g_x1);

    cudaFuncSetAttribute(qgemm_kernel<float>, cudaFuncAttributeMaxDynamicSharedMemorySize, QSMEM);
    cudaFuncSetAttribute(qgemm_kernel<bf16>,  cudaFuncAttributeMaxDynamicSharedMemorySize, QSMEM);

    // operand prep (batched)
    pack_fT3_kernel<<<dim3((DD*NN*RKK + 255)/256, 1, 3), 256>>>(f_qk, f_v, f_know, BqkvT, BknT);
    cvt_fp8_kernel<<<(DD*DD + 255)/256, 256>>>(W_O, WOb, DD*DD);
    transpose_q3_kernel<<<dim3(DD/32, NRK/32, 3), dim3(32,8)>>>(r_qk, r_v, r_know, rqkT, rvT, rknT);

    // --- attention circuit ---
    ln_kernel<<<BSZ, 256>>>(x, gamma1, beta1, nx);

    qgemm_kernel<bf16><<<dim3(2*NR/128, BSZ/128), 256, QSMEM>>>(nx, BqkvT, allh, nullptr, INV_FEAT, BSZ, 2*NR, DD);

    combineT_kernel<<<BSZ, 256>>>(allh,      2*NR, w_fq, w_fk, w_rq, w_rk, Tqk, Tqk + (size_t)BSZ*NR, RR);
    combineT_kernel<<<BSZ, 256>>>(allh + NR, 2*NR, w_fv, nullptr, w_rv, nullptr, Tv, nullptr, RR);

    qgemm_kernel<bf16><<<dim3(DD/128, 2*BSZ/128), 256, QSMEM>>>(Tqk, rqkT, QKb, nullptr, INV_REST, 2*BSZ, DD, NR);
    qgemm_kernel<bf16><<<dim3(DD/128, BSZ/128), 256, QSMEM>>>(Tv, rvT, Vb, nullptr, INV_REST, BSZ, DD, NR);

    attn_mma_kernel<<<dim3(SS/64, HH, BB), 128>>>(QKb, QKb + (size_t)BSZ*DD, Vb, attn);

    // x1 = x + attn @ W_O^T  (B^T = W_O)
    qgemm_kernel<float><<<dim3(DD/128, BSZ/128), 256, QSMEM>>>(attn, WOb, x1, x, INV_WO, BSZ, DD, DD);

    // --- knowledge circuit ---
    ln_kernel<<<BSZ, 256>>>(x1, gamma2, beta2, nx);
    qgemm_kernel<bf16><<<dim3(NRK/128, BSZ/128), 256, QSMEM>>>(nx, BknT, allh, nullptr, INV_FEAT, BSZ, NRK, DD);
    combineT_kernel<<<BSZ, 256>>>(allh, NRK, w_know_f, nullptr, w_know_r, nullptr, Tkn, nullptr, RKK);
    qgemm_kernel<float><<<dim3(DD/128, BSZ/128), 256, QSMEM>>>(Tkn, rknT, out, x1, INV_REST, BSZ, DD, NRK);
}

// round 11
// speedup vs baseline: 1.3251x; 1.3251x over previous
#include <cuda_runtime.h>
#include <cuda_bf16.h>
#include <math.h>
#include <stdint.h>

// Problem constants
#define BB 2
#define SS 2048
#define DD 1024
#define HH 16
#define RR 64
#define NN 32
#define RKK 128
#define DHH 64
#define BSZ (BB*SS)
#define NR (NN*RR)           // 2048
#define NRK (NN*RKK)         // 4096
#define LN_EPS 1e-5f

typedef __nv_bfloat16 bf16;
typedef uint8_t fp8;

// quantization scales (powers of 2)
#define SQ_ACT  16.0f
#define SQ_W    512.0f
#define SQ_T    32.0f
#define SQ_ATTN 64.0f
#define INV_FEAT (1.0f/(SQ_ACT*SQ_W))
#define INV_REST (1.0f/(SQ_T*SQ_W))
#define INV_WO   (1.0f/(SQ_ATTN*SQ_W))

// ---------------- scratch ----------------------------------------------------
__device__ fp8   g_BqkvT[(size_t)2*NR*DD];
__device__ fp8   g_BknT[(size_t)NRK*DD];
__device__ fp8   g_WOb[(size_t)DD*DD];
__device__ fp8   g_rqkT[(size_t)DD*NR];
__device__ fp8   g_rvT [(size_t)DD*NR];
__device__ fp8   g_rknT[(size_t)DD*NRK];
__device__ fp8   g_nx [BSZ*DD];
__device__ bf16  g_allh[(size_t)BSZ*4096];
__device__ fp8   g_Tqk[(size_t)2*BSZ*NR];
__device__ fp8   g_Tv [(size_t)BSZ*NR];
__device__ fp8   g_Tkn[(size_t)BSZ*NRK];
__device__ bf16  g_QKb[(size_t)2*BSZ*DD];
__device__ bf16  g_Vb[BSZ*DD];
__device__ fp8   g_attn[BSZ*DD];
__device__ float g_x1[BSZ*DD];

// ---------------- helpers ----------------------------------------------------
__device__ __forceinline__ uint32_t smem_u32(const void* p) {
    return (uint32_t)__cvta_generic_to_shared(p);
}
__device__ __forceinline__ void cp16(uint32_t saddr, const void* gaddr) {
    asm volatile("cp.async.cg.shared.global [%0], [%1], 16;\n" :: "r"(saddr), "l"(gaddr));
}
__device__ __forceinline__ void cp_commit() { asm volatile("cp.async.commit_group;\n"); }
template<int N> __device__ __forceinline__ void cp_wait() {
    asm volatile("cp.async.wait_group %0;\n" :: "n"(N));
}
__device__ __forceinline__ void ldsm_x4(uint32_t& r0, uint32_t& r1, uint32_t& r2, uint32_t& r3, uint32_t addr) {
    asm volatile("ldmatrix.sync.aligned.m8n8.x4.shared.b16 {%0,%1,%2,%3}, [%4];\n"
                 : "=r"(r0), "=r"(r1), "=r"(r2), "=r"(r3) : "r"(addr));
}
__device__ __forceinline__ void ldsm_x4_t(uint32_t& r0, uint32_t& r1, uint32_t& r2, uint32_t& r3, uint32_t addr) {
    asm volatile("ldmatrix.sync.aligned.m8n8.x4.trans.shared.b16 {%0,%1,%2,%3}, [%4];\n"
                 : "=r"(r0), "=r"(r1), "=r"(r2), "=r"(r3) : "r"(addr));
}
__device__ __forceinline__ void mma16816(float* d, const uint32_t* a, const uint32_t* b) {
    asm volatile("mma.sync.aligned.m16n8k16.row.col.f32.bf16.bf16.f32 "
                 "{%0,%1,%2,%3}, {%4,%5,%6,%7}, {%8,%9}, {%0,%1,%2,%3};\n"
                 : "+f"(d[0]), "+f"(d[1]), "+f"(d[2]), "+f"(d[3])
                 : "r"(a[0]), "r"(a[1]), "r"(a[2]), "r"(a[3]), "r"(b[0]), "r"(b[1]));
}
__device__ __forceinline__ void mma16832fp8(float* d, const uint32_t* a, const uint32_t* b) {
    asm volatile("mma.sync.aligned.m16n8k32.row.col.f32.e4m3.e4m3.f32 "
                 "{%0,%1,%2,%3}, {%4,%5,%6,%7}, {%8,%9}, {%0,%1,%2,%3};\n"
                 : "+f"(d[0]), "+f"(d[1]), "+f"(d[2]), "+f"(d[3])
                 : "r"(a[0]), "r"(a[1]), "r"(a[2]), "r"(a[3]), "r"(b[0]), "r"(b[1]));
}
__device__ __forceinline__ uint32_t pack_bf16(float x, float y) {
    __nv_bfloat162 t = __floats2bfloat162_rn(x, y);
    return *(uint32_t*)&t;
}
__device__ __forceinline__ uint16_t pack_fp8x2(float lo, float hi) {
    uint16_t v;
    asm("cvt.rn.satfinite.e4m3x2.f32 %0, %1, %2;" : "=h"(v) : "f"(hi), "f"(lo));
    return v;
}
__device__ __forceinline__ fp8 cvt_fp8(float x) {
    uint16_t v;
    asm("cvt.rn.satfinite.e4m3x2.f32 %0, %1, %2;" : "=h"(v) : "f"(0.f), "f"(x));
    return (fp8)(v & 0xFF);
}

// ================== FP8 tensor-core GEMM =====================================
// C[M,Nc] = invs*(A[M,K] @ Bt[Nc,K]^T)(+Res). 128x128 CTA, TK=64B,
// 2-stage cp.async (R8-proven structure), 4 warps x (64x64) warp tiles
// to cut smem ldsm read amplification from 6x8KB to 4x8KB per K-iter.
#define QSTR 80

template<typename OutT>
__global__ __launch_bounds__(128, 2)
void qgemm_kernel(const fp8* __restrict__ A, const fp8* __restrict__ Bt,
                  OutT* __restrict__ C, const float* __restrict__ Res,
                  float invs, int M, int Nc, int K) {
    __shared__ fp8 As[2][128][QSTR];
    __shared__ fp8 Bs[2][128][QSTR];
    int tid = threadIdx.x;
    int lane = tid & 31;
    int warp = tid >> 5;
    int warp_m = warp & 1;      // 2 x 64 rows
    int warp_n = warp >> 1;     // 2 x 64 cols

    const fp8* Ab = A + (size_t)blockIdx.y * 128 * K;
    const fp8* Bb = Bt + (size_t)blockIdx.x * 128 * K;

    float acc[4][8][4];
    #pragma unroll
    for (int i = 0; i < 4; i++)
        #pragma unroll
        for (int j = 0; j < 8; j++)
            #pragma unroll
            for (int v = 0; v < 4; v++) acc[i][j][v] = 0.f;

    // loader: each of 128 threads owns one row, 4x cp16 per matrix (64B row)
    int ldrow = tid;

    // prologue: stage 0
    {
        uint32_t sa = smem_u32(&As[0][ldrow][0]);
        uint32_t sb = smem_u32(&Bs[0][ldrow][0]);
        const fp8* ag = Ab + (size_t)ldrow * K;
        const fp8* bg = Bb + (size_t)ldrow * K;
        #pragma unroll
        for (int c = 0; c < 64; c += 16) { cp16(sa + c, ag + c); cp16(sb + c, bg + c); }
    }
    cp_commit();

    int KT = K >> 6;
    for (int kt = 0; kt < KT; kt++) {
        if (kt + 1 < KT) {
            int st = (kt + 1) & 1;
            int k0 = (kt + 1) * 64;
            uint32_t sa = smem_u32(&As[st][ldrow][0]);
            uint32_t sb = smem_u32(&Bs[st][ldrow][0]);
            const fp8* ag = Ab + (size_t)ldrow * K + k0;
            const fp8* bg = Bb + (size_t)ldrow * K + k0;
            #pragma unroll
            for (int c = 0; c < 64; c += 16) { cp16(sa + c, ag + c); cp16(sb + c, bg + c); }
            cp_commit();
            cp_wait<1>();
        } else {
            cp_wait<0>();
        }
        __syncthreads();
        int st = kt & 1;
        #pragma unroll
        for (int kk = 0; kk < 64; kk += 32) {
            uint32_t af[4][4];
            #pragma unroll
            for (int i = 0; i < 4; i++) {
                int row = warp_m * 64 + i * 16 + (lane & 15);
                int col = kk + (lane >> 4) * 16;
                ldsm_x4(af[i][0], af[i][1], af[i][2], af[i][3], smem_u32(&As[st][row][col]));
            }
            uint32_t bfr[8][2];
            #pragma unroll
            for (int np = 0; np < 4; np++) {
                int row = warp_n * 64 + np * 16 + (lane & 7) + ((lane & 16) ? 8 : 0);
                int col = kk + ((lane & 8) ? 16 : 0);
                uint32_t r0, r1, r2, r3;
                ldsm_x4(r0, r1, r2, r3, smem_u32(&Bs[st][row][col]));
                bfr[np*2][0] = r0; bfr[np*2][1] = r1;
                bfr[np*2+1][0] = r2; bfr[np*2+1][1] = r3;
            }
            #pragma unroll
            for (int i = 0; i < 4; i++)
                #pragma unroll
                for (int j = 0; j < 8; j++)
                    mma16832fp8(acc[i][j], af[i], bfr[j]);
        }
        __syncthreads();
    }

    size_t blockRow = (size_t)blockIdx.y * 128;
    size_t blockCol = (size_t)blockIdx.x * 128;
    #pragma unroll
    for (int i = 0; i < 4; i++) {
        size_t r0 = blockRow + warp_m * 64 + i * 16 + (lane >> 2);
        #pragma unroll
        for (int j = 0; j < 8; j++) {
            size_t c0 = blockCol + warp_n * 64 + j * 8 + (lane & 3) * 2;
            float a0 = acc[i][j][0] * invs, a1 = acc[i][j][1] * invs;
            float a2 = acc[i][j][2] * invs, a3 = acc[i][j][3] * invs;
            if constexpr (sizeof(OutT) == 4) {
                float2 v0 = make_float2(a0, a1);
                float2 v1 = make_float2(a2, a3);
                if (Res) {
                    const float2 q0 = *(const float2*)(Res + r0 * Nc + c0);
                    const float2 q1 = *(const float2*)(Res + (r0 + 8) * Nc + c0);
                    v0.x += q0.x; v0.y += q0.y; v1.x += q1.x; v1.y += q1.y;
                }
                *(float2*)((float*)C + r0 * Nc + c0) = v0;
                *(float2*)((float*)C + (r0 + 8) * Nc + c0) = v1;
            } else {
                *(uint32_t*)((bf16*)C + r0 * Nc + c0)       = pack_bf16(a0, a1);
                *(uint32_t*)((bf16*)C + (r0 + 8) * Nc + c0) = pack_bf16(a2, a3);
            }
        }
    }
}

// ---------------- batched pack f[n,d,r] -> fp8 B^T ---------------------------
__global__ void pack_fT3_kernel(const float* __restrict__ f_qk, const float* __restrict__ f_v,
                                const float* __restrict__ f_know,
                                fp8* __restrict__ BqkvT, fp8* __restrict__ BknT) {
    int z = blockIdx.z;
    const float* in = (z == 0) ? f_qk : (z == 1) ? f_v : f_know;
    int Rr = (z == 2) ? RKK : RR;
    fp8* out = (z == 2) ? BknT : (BqkvT + (z == 1 ? (size_t)NR * DD : 0));
    int total = DD * NN * Rr;
    int idx = blockIdx.x * blockDim.x + threadIdx.x;
    if (idx >= total) return;
    int d = idx & (DD - 1);
    int col = idx >> 10;
    int n = col / Rr;
    int r = col - n * Rr;
    out[(size_t)col * DD + d] = cvt_fp8(in[((size_t)n * DD + d) * Rr + r] * SQ_W);
}

__global__ void cvt_fp8_kernel(const float* __restrict__ in, fp8* __restrict__ out, int n) {
    int i = blockIdx.x * blockDim.x + threadIdx.x;
    if (i < n) out[i] = cvt_fp8(in[i] * SQ_W);
}

__global__ void transpose_q3_kernel(const float* __restrict__ r_qk, const float* __restrict__ r_v,
                                    const float* __restrict__ r_know,
                                    fp8* __restrict__ rqkT, fp8* __restrict__ rvT,
                                    fp8* __restrict__ rknT) {
    int z = blockIdx.z;
    const float* in = (z == 0) ? r_qk : (z == 1) ? r_v : r_know;
    fp8* out = (z == 0) ? rqkT : (z == 1) ? rvT : rknT;
    int rows = (z == 2) ? NRK : NR;
    if (blockIdx.y * 32 >= rows) return;
    __shared__ float tile[32][33];
    int x = blockIdx.x * 32 + threadIdx.x;
    int y = blockIdx.y * 32 + threadIdx.y;
    #pragma unroll
    for (int i = 0; i < 32; i += 8)
        tile[threadIdx.y + i][threadIdx.x] = in[(size_t)(y + i) * DD + x];
    __syncthreads();
    x = blockIdx.y * 32 + threadIdx.x;
    y = blockIdx.x * 32 + threadIdx.y;
    #pragma unroll
    for (int i = 0; i < 32; i += 8)
        out[(size_t)(y + i) * rows + x] = cvt_fp8(tile[threadIdx.x][threadIdx.y + i] * SQ_W);
}

// ---------------- LayerNorm (fp8 out) ----------------------------------------
__global__ void ln_kernel(const float* __restrict__ x, const float* __restrict__ g,
                          const float* __restrict__ b, fp8* __restrict__ out) {
    int row = blockIdx.x;
    const float* xr = x + (size_t)row * DD;
    int c = threadIdx.x * 4;
    float4 xv = *(const float4*)(xr + c);
    float s  = xv.x + xv.y + xv.z + xv.w;
    float sq = xv.x*xv.x + xv.y*xv.y + xv.z*xv.z + xv.w*xv.w;
    #pragma unroll
    for (int o = 16; o > 0; o >>= 1) {
        s  += __shfl_xor_sync(0xffffffffu, s,  o);
        sq += __shfl_xor_sync(0xffffffffu, sq, o);
    }
    __shared__ float ss[8], ssq[8];
    __shared__ float mean_s, rstd_s;
    int wid = threadIdx.x >> 5, lid = threadIdx.x & 31;
    if (lid == 0) { ss[wid] = s; ssq[wid] = sq; }
    __syncthreads();
    if (threadIdx.x == 0) {
        float S = 0.f, SQ = 0.f;
        #pragma unroll
        for (int i = 0; i < 8; i++) { S += ss[i]; SQ += ssq[i]; }
        float mu  = S * (1.f / DD);
        float var = SQ * (1.f / DD) - mu * mu;
        mean_s = mu;
        rstd_s = rsqrtf(var + LN_EPS);
    }
    __syncthreads();
    float mu = mean_s, rs = rstd_s;
    float4 gv = *(const float4*)(g + c);
    float4 bv = *(const float4*)(b + c);
    float o0 = (gv.x * (xv.x - mu) * rs + bv.x) * SQ_ACT;
    float o1 = (gv.y * (xv.y - mu) * rs + bv.y) * SQ_ACT;
    float o2 = (gv.z * (xv.z - mu) * rs + bv.z) * SQ_ACT;
    float o3 = (gv.w * (xv.w - mu) * rs + bv.w) * SQ_ACT;
    uint32_t pk = (uint32_t)pack_fp8x2(o0, o1) | ((uint32_t)pack_fp8x2(o2, o3) << 16);
    *(uint32_t*)(out + (size_t)row * DD + c) = pk;
}

// ---------------- fused combine + buildT (bf16 allh in, fp8 T out) -----------
__global__ void combineT_kernel(const bf16* __restrict__ allh, int stride,
                                const float* __restrict__ wf1, const float* __restrict__ wf2,
                                const float* __restrict__ wr1, const float* __restrict__ wr2,
                                fp8* __restrict__ T1, fp8* __restrict__ T2, int Rr) {
    int bs = blockIdx.x;
    int tid = threadIdx.x;
    __shared__ float h1s[RKK], h2s[RKK];
    __shared__ float wf1s[NN], wf2s[NN], wr1s[NN], wr2s[NN];
    if (tid < NN) {
        wf1s[tid] = wf1[(size_t)bs * NN + tid];
        wr1s[tid] = wr1[(size_t)bs * NN + tid] * SQ_T;
        if (wf2) { wf2s[tid] = wf2[(size_t)bs * NN + tid]; wr2s[tid] = wr2[(size_t)bs * NN + tid] * SQ_T; }
    }
    __syncthreads();
    if (tid < Rr) {
        const bf16* rowp = allh + (size_t)bs * stride;
        float a1 = 0.f, a2 = 0.f;
        #pragma unroll 8
        for (int n = 0; n < NN; n++) {
            float v = __bfloat162float(rowp[n * Rr + tid]);
            a1 += wf1s[n] * v;
            if (wf2) a2 += wf2s[n] * v;
        }
        h1s[tid] = a1;
        if (wf2) h2s[tid] = a2;
    }
    __syncthreads();
    int total = NN * Rr;
    fp8* T1row = T1 + (size_t)bs * total;
    fp8* T2row = wf2 ? (T2 + (size_t)bs * total) : nullptr;
    for (int i = tid; i < total; i += 256) {
        int n = i / Rr;
        int r = i - n * Rr;
        T1row[i] = cvt_fp8(wr1s[n] * h1s[r]);
        if (wf2) T2row[i] = cvt_fp8(wr2s[n] * h2s[r]);
    }
}

// ================= bf16 mma.sync flash attention (fp8 output) ================
#define KSTR 72
#define SC2 (0.125f * 1.44269504f)

__global__ __launch_bounds__(128)
void attn_mma_kernel(const bf16* __restrict__ Q, const bf16* __restrict__ K,
                     const bf16* __restrict__ V, fp8* __restrict__ O) {
    __shared__ bf16 Qs[64][KSTR];
    __shared__ bf16 Ks[2][64][KSTR];
    __shared__ bf16 Vs[2][64][KSTR];

    int qt = gridDim.x - 1 - blockIdx.x;
    int h = blockIdx.y, b = blockIdx.z;
    int tid = threadIdx.x;
    int lane = tid & 31, w = tid >> 5;
    size_t headoff = (size_t)h * DHH;

    const bf16* Qbase = Q + ((size_t)(b * SS + qt * 64)) * DD + headoff;
    const bf16* Kbase = K + ((size_t)b * SS) * DD + headoff;
    const bf16* Vbase = V + ((size_t)b * SS) * DD + headoff;

    #pragma unroll
    for (int i = 0; i < 4; i++) {
        int c = tid + i * 128;
        int row = c >> 3, off = (c & 7) * 8;
        cp16(smem_u32(&Qs[row][off]), Qbase + (size_t)row * DD + off);
    }
    cp_commit();
    #pragma unroll
    for (int i = 0; i < 4; i++) {
        int c = tid + i * 128;
        int row = c >> 3, off = (c & 7) * 8;
        cp16(smem_u32(&Ks[0][row][off]), Kbase + (size_t)row * DD + off);
        cp16(smem_u32(&Vs[0][row][off]), Vbase + (size_t)row * DD + off);
    }
    cp_commit();

    cp_wait<1>();
    __syncthreads();
    uint32_t aq[4][4];
    #pragma unroll
    for (int kc = 0; kc < 4; kc++) {
        int row = w * 16 + (lane & 15);
        int col = kc * 16 + (lane >> 4) * 8;
        ldsm_x4(aq[kc][0], aq[kc][1], aq[kc][2], aq[kc][3], smem_u32(&Qs[row][col]));
    }

    float acc_o[8][4];
    #pragma unroll
    for (int nt = 0; nt < 8; nt++)
        #pragma unroll
        for (int v = 0; v < 4; v++) acc_o[nt][v] = 0.f;
    float m[2] = {-INFINITY, -INFINITY};
    float l[2] = {0.f, 0.f};

    int ntiles = qt + 1;
    for (int j = 0; j < ntiles; j++) {
        int st = j & 1;
        if (j + 1 < ntiles) {
            const bf16* kb = Kbase + (size_t)(j + 1) * 64 * DD;
            const bf16* vb = Vbase + (size_t)(j + 1) * 64 * DD;
            #pragma unroll
            for (int i = 0; i < 4; i++) {
                int c = tid + i * 128;
                int row = c >> 3, off = (c & 7) * 8;
                cp16(smem_u32(&Ks[st ^ 1][row][off]), kb + (size_t)row * DD + off);
                cp16(smem_u32(&Vs[st ^ 1][row][off]), vb + (size_t)row * DD + off);
            }
            cp_commit();
            cp_wait<1>();
        } else {
            cp_wait<0>();
        }
        __syncthreads();

        float s[8][4];
        #pragma unroll
        for (int nt = 0; nt < 8; nt++)
            #pragma unroll
            for (int v = 0; v < 4; v++) s[nt][v] = 0.f;
        #pragma unroll
        for (int kc = 0; kc < 4; kc++) {
            uint32_t bk[8][2];
            #pragma unroll
            for (int np = 0; np < 4; np++) {
                int row = np * 16 + (lane & 7) + ((lane & 16) ? 8 : 0);
                int colk = kc * 16 + ((lane & 8) ? 8 : 0);
                uint32_t r0, r1, r2, r3;
                ldsm_x4(r0, r1, r2, r3, smem_u32(&Ks[st][row][colk]));
                bk[np*2][0] = r0; bk[np*2][1] = r1;
                bk[np*2+1][0] = r2; bk[np*2+1][1] = r3;
            }
            #pragma unroll
            for (int nt = 0; nt < 8; nt++)
                mma16816(s[nt], aq[kc], bk[nt]);
        }

        if (j == qt) {
            int r0 = w * 16 + (lane >> 2);
            int cb = (lane & 3) * 2;
            #pragma unroll
            for (int nt = 0; nt < 8; nt++) {
                #pragma unroll
                for (int v = 0; v < 4; v++) {
                    int col = nt * 8 + cb + (v & 1);
                    int row = r0 + ((v & 2) ? 8 : 0);
                    if (col > row) s[nt][v] = -INFINITY;
                }
            }
        }

        #pragma unroll
        for (int rh = 0; rh < 2; rh++) {
            float mt = -INFINITY;
            #pragma unroll
            for (int nt = 0; nt < 8; nt++)
                mt = fmaxf(mt, fmaxf(s[nt][rh*2], s[nt][rh*2+1]));
            mt = fmaxf(mt, __shfl_xor_sync(0xffffffffu, mt, 1));
            mt = fmaxf(mt, __shfl_xor_sync(0xffffffffu, mt, 2));
            float mn = fmaxf(m[rh], mt);
            float corr = exp2f((m[rh] - mn) * SC2);
            m[rh] = mn;
            float ls = 0.f;
            #pragma unroll
            for (int nt = 0; nt < 8; nt++) {
                float p0 = exp2f((s[nt][rh*2]   - mn) * SC2);
                float p1 = exp2f((s[nt][rh*2+1] - mn) * SC2);
                s[nt][rh*2] = p0; s[nt][rh*2+1] = p1;
                ls += p0 + p1;
            }
            ls += __shfl_xor_sync(0xffffffffu, ls, 1);
            ls += __shfl_xor_sync(0xffffffffu, ls, 2);
            l[rh] = l[rh] * corr + ls;
            #pragma unroll
            for (int nt = 0; nt < 8; nt++) {
                acc_o[nt][rh*2]   *= corr;
                acc_o[nt][rh*2+1] *= corr;
            }
        }

        #pragma unroll
        for (int kc = 0; kc < 4; kc++) {
            uint32_t pa[4];
            pa[0] = pack_bf16(s[2*kc][0],   s[2*kc][1]);
            pa[1] = pack_bf16(s[2*kc][2],   s[2*kc][3]);
            pa[2] = pack_bf16(s[2*kc+1][0], s[2*kc+1][1]);
            pa[3] = pack_bf16(s[2*kc+1][2], s[2*kc+1][3]);
            uint32_t bv[8][2];
            #pragma unroll
            for (int np = 0; np < 4; np++) {
                int kr = kc * 16 + (lane & 7) + ((lane & 16) ? 8 : 0);
                int col = np * 16 + ((lane & 8) ? 8 : 0);
                uint32_t r0, r1, r2, r3;
                ldsm_x4_t(r0, r1, r2, r3, smem_u32(&Vs[st][kr][col]));
                bv[np*2][0] = r0; bv[np*2+1][0] = r1;
                bv[np*2][1] = r2; bv[np*2+1][1] = r3;
            }
            #pragma unroll
            for (int nt = 0; nt < 8; nt++)
                mma16816(acc_o[nt], pa, bv[nt]);
        }
        __syncthreads();
    }

    float inv0 = SQ_ATTN / l[0];
    float inv1 = SQ_ATTN / l[1];
    int row0 = qt * 64 + w * 16 + (lane >> 2);
    fp8* Ob = O + ((size_t)b * SS) * DD + headoff;
    #pragma unroll
    for (int nt = 0; nt < 8; nt++) {
        int col = nt * 8 + (lane & 3) * 2;
        *(uint16_t*)(Ob + (size_t)row0 * DD + col)       = pack_fp8x2(acc_o[nt][0] * inv0, acc_o[nt][1] * inv0);
        *(uint16_t*)(Ob + (size_t)(row0 + 8) * DD + col) = pack_fp8x2(acc_o[nt][2] * inv1, acc_o[nt][3] * inv1);
    }
}

// ---------------- launch -----------------------------------------------------
extern "C" void kernel_launch(void* const* d_in, const int* in_sizes, int n_in,
                              void* d_out, int out_size) {
    const float* x       = (const float*)d_in[0];
    const float* f_qk    = (const float*)d_in[1];
    const float* f_v     = (const float*)d_in[2];
    const float* r_qk    = (const float*)d_in[3];
    const float* r_v     = (const float*)d_in[4];
    const float* f_know  = (const float*)d_in[5];
    const float* r_know  = (const float*)d_in[6];
    const float* W_O     = (const float*)d_in[7];
    const float* gamma1  = (const float*)d_in[8];
    const float* beta1   = (const float*)d_in[9];
    const float* gamma2  = (const float*)d_in[10];
    const float* beta2   = (const float*)d_in[11];
    const float* w_fq    = (const float*)d_in[12];
    const float* w_fk    = (const float*)d_in[13];
    const float* w_fv    = (const float*)d_in[14];
    const float* w_rq    = (const float*)d_in[15];
    const float* w_rk    = (const float*)d_in[16];
    const float* w_rv    = (const float*)d_in[17];
    const float* w_know_f= (const float*)d_in[18];
    const float* w_know_r= (const float*)d_in[19];
    float* out = (float*)d_out;

    fp8 *BqkvT, *BknT, *WOb, *rqkT, *rvT, *rknT, *nx, *Tqk, *Tv, *Tkn, *attn;
    bf16 *QKb, *Vb, *allh;
    float *x1;
    cudaGetSymbolAddress((void**)&BqkvT, g_BqkvT);
    cudaGetSymbolAddress((void**)&BknT, g_BknT);
    cudaGetSymbolAddress((void**)&WOb, g_WOb);
    cudaGetSymbolAddress((void**)&rqkT, g_rqkT);
    cudaGetSymbolAddress((void**)&rvT,  g_rvT);
    cudaGetSymbolAddress((void**)&rknT, g_rknT);
    cudaGetSymbolAddress((void**)&nx,  g_nx);
    cudaGetSymbolAddress((void**)&allh, g_allh);
    cudaGetSymbolAddress((void**)&Tqk, g_Tqk);
    cudaGetSymbolAddress((void**)&Tv,  g_Tv);
    cudaGetSymbolAddress((void**)&Tkn, g_Tkn);
    cudaGetSymbolAddress((void**)&QKb, g_QKb);
    cudaGetSymbolAddress((void**)&Vb,  g_Vb);
    cudaGetSymbolAddress((void**)&attn, g_attn);
    cudaGetSymbolAddress((void**)&x1, g_x1);

    // operand prep (batched)
    pack_fT3_kernel<<<dim3((DD*NN*RKK + 255)/256, 1, 3), 256>>>(f_qk, f_v, f_know, BqkvT, BknT);
    cvt_fp8_kernel<<<(DD*DD + 255)/256, 256>>>(W_O, WOb, DD*DD);
    transpose_q3_kernel<<<dim3(DD/32, NRK/32, 3), dim3(32,8)>>>(r_qk, r_v, r_know, rqkT, rvT, rknT);

    // --- attention circuit ---
    ln_kernel<<<BSZ, 256>>>(x, gamma1, beta1, nx);

    qgemm_kernel<bf16><<<dim3(2*NR/128, BSZ/128), 128>>>(nx, BqkvT, allh, nullptr, INV_FEAT, BSZ, 2*NR, DD);

    combineT_kernel<<<BSZ, 256>>>(allh,      2*NR, w_fq, w_fk, w_rq, w_rk, Tqk, Tqk + (size_t)BSZ*NR, RR);
    combineT_kernel<<<BSZ, 256>>>(allh + NR, 2*NR, w_fv, nullptr, w_rv, nullptr, Tv, nullptr, RR);

    qgemm_kernel<bf16><<<dim3(DD/128, 2*BSZ/128), 128>>>(Tqk, rqkT, QKb, nullptr, INV_REST, 2*BSZ, DD, NR);
    qgemm_kernel<bf16><<<dim3(DD/128, BSZ/128), 128>>>(Tv, rvT, Vb, nullptr, INV_REST, BSZ, DD, NR);

    attn_mma_kernel<<<dim3(SS/64, HH, BB), 128>>>(QKb, QKb + (size_t)BSZ*DD, Vb, attn);

    // x1 = x + attn @ W_O^T  (B^T = W_O)
    qgemm_kernel<float><<<dim3(DD/128, BSZ/128), 128>>>(attn, WOb, x1, x, INV_WO, BSZ, DD, DD);

    // --- knowledge circuit ---
    ln_kernel<<<BSZ, 256>>>(x1, gamma2, beta2, nx);
    qgemm_kernel<bf16><<<dim3(NRK/128, BSZ/128), 128>>>(nx, BknT, allh, nullptr, INV_FEAT, BSZ, NRK, DD);
    combineT_kernel<<<BSZ, 256>>>(allh, NRK, w_know_f, nullptr, w_know_r, nullptr, Tkn, nullptr, RKK);
    qgemm_kernel<float><<<dim3(DD/128, BSZ/128), 128>>>(Tkn, rknT, out, x1, INV_REST, BSZ, DD, NRK);
}

// round 13
// speedup vs baseline: 1.5024x; 1.1339x over previous
#include <cuda_runtime.h>
#include <cuda_bf16.h>
#include <math.h>
#include <stdint.h>

// Problem constants
#define BB 2
#define SS 2048
#define DD 1024
#define HH 16
#define RR 64
#define NN 32
#define RKK 128
#define DHH 64
#define BSZ (BB*SS)
#define NR (NN*RR)           // 2048
#define NRK (NN*RKK)         // 4096
#define LN_EPS 1e-5f

typedef __nv_bfloat16 bf16;
typedef uint8_t fp8;

// quantization scales (powers of 2)
#define SQ_ACT  16.0f
#define SQ_W    512.0f
#define SQ_T    32.0f
#define SQ_ATTN 64.0f
#define INV_FEAT (1.0f/(SQ_ACT*SQ_W))
#define INV_REST (1.0f/(SQ_T*SQ_W))
#define INV_WO   (1.0f/(SQ_ATTN*SQ_W))

// ---------------- scratch ----------------------------------------------------
__device__ fp8   g_BqkvT[(size_t)2*NR*DD];
__device__ fp8   g_BknT[(size_t)NRK*DD];
__device__ fp8   g_WOb[(size_t)DD*DD];
__device__ fp8   g_rqkT[(size_t)DD*NR];
__device__ fp8   g_rvT [(size_t)DD*NR];
__device__ fp8   g_rknT[(size_t)DD*NRK];
__device__ fp8   g_nx [BSZ*DD];
__device__ bf16  g_allh[(size_t)BSZ*4096];
__device__ fp8   g_Tqk[(size_t)2*BSZ*NR];
__device__ fp8   g_Tv [(size_t)BSZ*NR];
__device__ fp8   g_Tkn[(size_t)BSZ*NRK];
__device__ bf16  g_QKb[(size_t)2*BSZ*DD];
__device__ bf16  g_Vb[BSZ*DD];
__device__ fp8   g_attn[BSZ*DD];
__device__ float g_x1[BSZ*DD];

// ---------------- helpers ----------------------------------------------------
__device__ __forceinline__ uint32_t smem_u32(const void* p) {
    return (uint32_t)__cvta_generic_to_shared(p);
}
__device__ __forceinline__ void cp16(uint32_t saddr, const void* gaddr) {
    asm volatile("cp.async.cg.shared.global [%0], [%1], 16;\n" :: "r"(saddr), "l"(gaddr));
}
__device__ __forceinline__ void cp_commit() { asm volatile("cp.async.commit_group;\n"); }
template<int N> __device__ __forceinline__ void cp_wait() {
    asm volatile("cp.async.wait_group %0;\n" :: "n"(N));
}
__device__ __forceinline__ void ldsm_x4(uint32_t& r0, uint32_t& r1, uint32_t& r2, uint32_t& r3, uint32_t addr) {
    asm volatile("ldmatrix.sync.aligned.m8n8.x4.shared.b16 {%0,%1,%2,%3}, [%4];\n"
                 : "=r"(r0), "=r"(r1), "=r"(r2), "=r"(r3) : "r"(addr));
}
__device__ __forceinline__ void ldsm_x4_t(uint32_t& r0, uint32_t& r1, uint32_t& r2, uint32_t& r3, uint32_t addr) {
    asm volatile("ldmatrix.sync.aligned.m8n8.x4.trans.shared.b16 {%0,%1,%2,%3}, [%4];\n"
                 : "=r"(r0), "=r"(r1), "=r"(r2), "=r"(r3) : "r"(addr));
}
__device__ __forceinline__ void mma16816(float* d, const uint32_t* a, const uint32_t* b) {
    asm volatile("mma.sync.aligned.m16n8k16.row.col.f32.bf16.bf16.f32 "
                 "{%0,%1,%2,%3}, {%4,%5,%6,%7}, {%8,%9}, {%0,%1,%2,%3};\n"
                 : "+f"(d[0]), "+f"(d[1]), "+f"(d[2]), "+f"(d[3])
                 : "r"(a[0]), "r"(a[1]), "r"(a[2]), "r"(a[3]), "r"(b[0]), "r"(b[1]));
}
__device__ __forceinline__ void mma16832fp8(float* d, const uint32_t* a, const uint32_t* b) {
    asm volatile("mma.sync.aligned.m16n8k32.row.col.f32.e4m3.e4m3.f32 "
                 "{%0,%1,%2,%3}, {%4,%5,%6,%7}, {%8,%9}, {%0,%1,%2,%3};\n"
                 : "+f"(d[0]), "+f"(d[1]), "+f"(d[2]), "+f"(d[3])
                 : "r"(a[0]), "r"(a[1]), "r"(a[2]), "r"(a[3]), "r"(b[0]), "r"(b[1]));
}
__device__ __forceinline__ uint32_t pack_bf16(float x, float y) {
    __nv_bfloat162 t = __floats2bfloat162_rn(x, y);
    return *(uint32_t*)&t;
}
__device__ __forceinline__ uint16_t pack_fp8x2(float lo, float hi) {
    uint16_t v;
    asm("cvt.rn.satfinite.e4m3x2.f32 %0, %1, %2;" : "=h"(v) : "f"(hi), "f"(lo));
    return v;
}
__device__ __forceinline__ fp8 cvt_fp8(float x) {
    uint16_t v;
    asm("cvt.rn.satfinite.e4m3x2.f32 %0, %1, %2;" : "=h"(v) : "f"(0.f), "f"(x));
    return (fp8)(v & 0xFF);
}

// ================== FP8 tensor-core GEMM (R8-proven configuration) ===========
// C[M,Nc] = invs*(A[M,K] @ Bt[Nc,K]^T)(+Res). 128x128 CTA, TK=64B,
// 256 threads, 8 warps (2M x 4N, 64x32 warp tiles), 2-stage cp.async.
#define QSTR 80

template<typename OutT>
__global__ __launch_bounds__(256, 2)
void qgemm_kernel(const fp8* __restrict__ A, const fp8* __restrict__ Bt,
                  OutT* __restrict__ C, const float* __restrict__ Res,
                  float invs, int M, int Nc, int K) {
    __shared__ fp8 As[2][128][QSTR];
    __shared__ fp8 Bs[2][128][QSTR];
    int tid = threadIdx.x;
    int lane = tid & 31;
    int warp = tid >> 5;
    int warp_m = warp & 1;      // 2 x 64 rows
    int warp_n = warp >> 1;     // 4 x 32 cols

    const fp8* Ab = A + (size_t)blockIdx.y * 128 * K;
    const fp8* Bb = Bt + (size_t)blockIdx.x * 128 * K;

    float acc[4][4][4];
    #pragma unroll
    for (int i = 0; i < 4; i++)
        #pragma unroll
        for (int j = 0; j < 4; j++)
            #pragma unroll
            for (int v = 0; v < 4; v++) acc[i][j][v] = 0.f;

    int ldrow = tid >> 1;             // 0..127
    int ldc   = (tid & 1) * 32;       // 0 or 32

    // prologue: stage 0
    {
        uint32_t sa = smem_u32(&As[0][ldrow][ldc]);
        uint32_t sb = smem_u32(&Bs[0][ldrow][ldc]);
        cp16(sa,      Ab + (size_t)ldrow * K + ldc);
        cp16(sa + 16, Ab + (size_t)ldrow * K + ldc + 16);
        cp16(sb,      Bb + (size_t)ldrow * K + ldc);
        cp16(sb + 16, Bb + (size_t)ldrow * K + ldc + 16);
    }
    cp_commit();

    int KT = K >> 6;
    for (int kt = 0; kt < KT; kt++) {
        if (kt + 1 < KT) {
            int st = (kt + 1) & 1;
            int k0 = (kt + 1) * 64;
            uint32_t sa = smem_u32(&As[st][ldrow][ldc]);
            uint32_t sb = smem_u32(&Bs[st][ldrow][ldc]);
            cp16(sa,      Ab + (size_t)ldrow * K + k0 + ldc);
            cp16(sa + 16, Ab + (size_t)ldrow * K + k0 + ldc + 16);
            cp16(sb,      Bb + (size_t)ldrow * K + k0 + ldc);
            cp16(sb + 16, Bb + (size_t)ldrow * K + k0 + ldc + 16);
            cp_commit();
            cp_wait<1>();
        } else {
            cp_wait<0>();
        }
        __syncthreads();
        int st = kt & 1;
        #pragma unroll
        for (int kk = 0; kk < 64; kk += 32) {
            uint32_t af[4][4];
            #pragma unroll
            for (int i = 0; i < 4; i++) {
                int row = warp_m * 64 + i * 16 + (lane & 15);
                int col = kk + (lane >> 4) * 16;
                ldsm_x4(af[i][0], af[i][1], af[i][2], af[i][3], smem_u32(&As[st][row][col]));
            }
            uint32_t bfr[4][2];
            #pragma unroll
            for (int np = 0; np < 2; np++) {
                int row = warp_n * 32 + np * 16 + (lane & 7) + ((lane & 16) ? 8 : 0);
                int col = kk + ((lane & 8) ? 16 : 0);
                uint32_t r0, r1, r2, r3;
                ldsm_x4(r0, r1, r2, r3, smem_u32(&Bs[st][row][col]));
                bfr[np*2][0] = r0; bfr[np*2][1] = r1;
                bfr[np*2+1][0] = r2; bfr[np*2+1][1] = r3;
            }
            #pragma unroll
            for (int i = 0; i < 4; i++)
                #pragma unroll
                for (int j = 0; j < 4; j++)
                    mma16832fp8(acc[i][j], af[i], bfr[j]);
        }
        __syncthreads();
    }

    size_t blockRow = (size_t)blockIdx.y * 128;
    size_t blockCol = (size_t)blockIdx.x * 128;
    #pragma unroll
    for (int i = 0; i < 4; i++) {
        size_t r0 = blockRow + warp_m * 64 + i * 16 + (lane >> 2);
        #pragma unroll
        for (int j = 0; j < 4; j++) {
            size_t c0 = blockCol + warp_n * 32 + j * 8 + (lane & 3) * 2;
            float a0 = acc[i][j][0] * invs, a1 = acc[i][j][1] * invs;
            float a2 = acc[i][j][2] * invs, a3 = acc[i][j][3] * invs;
            if constexpr (sizeof(OutT) == 4) {
                float2 v0 = make_float2(a0, a1);
                float2 v1 = make_float2(a2, a3);
                if (Res) {
                    const float2 q0 = *(const float2*)(Res + r0 * Nc + c0);
                    const float2 q1 = *(const float2*)(Res + (r0 + 8) * Nc + c0);
                    v0.x += q0.x; v0.y += q0.y; v1.x += q1.x; v1.y += q1.y;
                }
                *(float2*)((float*)C + r0 * Nc + c0) = v0;
                *(float2*)((float*)C + (r0 + 8) * Nc + c0) = v1;
            } else {
                *(uint32_t*)((bf16*)C + r0 * Nc + c0)       = pack_bf16(a0, a1);
                *(uint32_t*)((bf16*)C + (r0 + 8) * Nc + c0) = pack_bf16(a2, a3);
            }
        }
    }
}

// ---------------- batched pack f[n,d,r] -> fp8 B^T ---------------------------
__global__ void pack_fT3_kernel(const float* __restrict__ f_qk, const float* __restrict__ f_v,
                                const float* __restrict__ f_know,
                                fp8* __restrict__ BqkvT, fp8* __restrict__ BknT) {
    int z = blockIdx.z;
    const float* in = (z == 0) ? f_qk : (z == 1) ? f_v : f_know;
    int Rr = (z == 2) ? RKK : RR;
    fp8* out = (z == 2) ? BknT : (BqkvT + (z == 1 ? (size_t)NR * DD : 0));
    int total = DD * NN * Rr;
    int idx = blockIdx.x * blockDim.x + threadIdx.x;
    if (idx >= total) return;
    int d = idx & (DD - 1);
    int col = idx >> 10;
    int n = col / Rr;
    int r = col - n * Rr;
    out[(size_t)col * DD + d] = cvt_fp8(in[((size_t)n * DD + d) * Rr + r] * SQ_W);
}

__global__ void cvt_fp8_kernel(const float* __restrict__ in, fp8* __restrict__ out, int n) {
    int i = blockIdx.x * blockDim.x + threadIdx.x;
    if (i < n) out[i] = cvt_fp8(in[i] * SQ_W);
}

__global__ void transpose_q3_kernel(const float* __restrict__ r_qk, const float* __restrict__ r_v,
                                    const float* __restrict__ r_know,
                                    fp8* __restrict__ rqkT, fp8* __restrict__ rvT,
                                    fp8* __restrict__ rknT) {
    int z = blockIdx.z;
    const float* in = (z == 0) ? r_qk : (z == 1) ? r_v : r_know;
    fp8* out = (z == 0) ? rqkT : (z == 1) ? rvT : rknT;
    int rows = (z == 2) ? NRK : NR;
    if (blockIdx.y * 32 >= rows) return;
    __shared__ float tile[32][33];
    int x = blockIdx.x * 32 + threadIdx.x;
    int y = blockIdx.y * 32 + threadIdx.y;
    #pragma unroll
    for (int i = 0; i < 32; i += 8)
        tile[threadIdx.y + i][threadIdx.x] = in[(size_t)(y + i) * DD + x];
    __syncthreads();
    x = blockIdx.y * 32 + threadIdx.x;
    y = blockIdx.x * 32 + threadIdx.y;
    #pragma unroll
    for (int i = 0; i < 32; i += 8)
        out[(size_t)(y + i) * rows + x] = cvt_fp8(tile[threadIdx.x][threadIdx.y + i] * SQ_W);
}

// ---------------- LayerNorm (fp8 out) ----------------------------------------
__global__ void ln_kernel(const float* __restrict__ x, const float* __restrict__ g,
                          const float* __restrict__ b, fp8* __restrict__ out) {
    int row = blockIdx.x;
    const float* xr = x + (size_t)row * DD;
    int c = threadIdx.x * 4;
    float4 xv = *(const float4*)(xr + c);
    float s  = xv.x + xv.y + xv.z + xv.w;
    float sq = xv.x*xv.x + xv.y*xv.y + xv.z*xv.z + xv.w*xv.w;
    #pragma unroll
    for (int o = 16; o > 0; o >>= 1) {
        s  += __shfl_xor_sync(0xffffffffu, s,  o);
        sq += __shfl_xor_sync(0xffffffffu, sq, o);
    }
    __shared__ float ss[8], ssq[8];
    __shared__ float mean_s, rstd_s;
    int wid = threadIdx.x >> 5, lid = threadIdx.x & 31;
    if (lid == 0) { ss[wid] = s; ssq[wid] = sq; }
    __syncthreads();
    if (threadIdx.x == 0) {
        float S = 0.f, SQ = 0.f;
        #pragma unroll
        for (int i = 0; i < 8; i++) { S += ss[i]; SQ += ssq[i]; }
        float mu  = S * (1.f / DD);
        float var = SQ * (1.f / DD) - mu * mu;
        mean_s = mu;
        rstd_s = rsqrtf(var + LN_EPS);
    }
    __syncthreads();
    float mu = mean_s, rs = rstd_s;
    float4 gv = *(const float4*)(g + c);
    float4 bv = *(const float4*)(b + c);
    float o0 = (gv.x * (xv.x - mu) * rs + bv.x) * SQ_ACT;
    float o1 = (gv.y * (xv.y - mu) * rs + bv.y) * SQ_ACT;
    float o2 = (gv.z * (xv.z - mu) * rs + bv.z) * SQ_ACT;
    float o3 = (gv.w * (xv.w - mu) * rs + bv.w) * SQ_ACT;
    uint32_t pk = (uint32_t)pack_fp8x2(o0, o1) | ((uint32_t)pack_fp8x2(o2, o3) << 16);
    *(uint32_t*)(out + (size_t)row * DD + c) = pk;
}

// ---------------- fused combine + buildT (bf16 allh in, fp8 T out) -----------
__global__ void combineT_kernel(const bf16* __restrict__ allh, int stride,
                                const float* __restrict__ wf1, const float* __restrict__ wf2,
                                const float* __restrict__ wr1, const float* __restrict__ wr2,
                                fp8* __restrict__ T1, fp8* __restrict__ T2, int Rr) {
    int bs = blockIdx.x;
    int tid = threadIdx.x;
    __shared__ float h1s[RKK], h2s[RKK];
    __shared__ float wf1s[NN], wf2s[NN], wr1s[NN], wr2s[NN];
    if (tid < NN) {
        wf1s[tid] = wf1[(size_t)bs * NN + tid];
        wr1s[tid] = wr1[(size_t)bs * NN + tid] * SQ_T;
        if (wf2) { wf2s[tid] = wf2[(size_t)bs * NN + tid]; wr2s[tid] = wr2[(size_t)bs * NN + tid] * SQ_T; }
    }
    __syncthreads();
    if (tid < Rr) {
        const bf16* rowp = allh + (size_t)bs * stride;
        float a1 = 0.f, a2 = 0.f;
        #pragma unroll 8
        for (int n = 0; n < NN; n++) {
            float v = __bfloat162float(rowp[n * Rr + tid]);
            a1 += wf1s[n] * v;
            if (wf2) a2 += wf2s[n] * v;
        }
        h1s[tid] = a1;
        if (wf2) h2s[tid] = a2;
    }
    __syncthreads();
    int total = NN * Rr;
    fp8* T1row = T1 + (size_t)bs * total;
    fp8* T2row = wf2 ? (T2 + (size_t)bs * total) : nullptr;
    for (int i = tid; i < total; i += 256) {
        int n = i / Rr;
        int r = i - n * Rr;
        T1row[i] = cvt_fp8(wr1s[n] * h1s[r]);
        if (wf2) T2row[i] = cvt_fp8(wr2s[n] * h2s[r]);
    }
}

// ================= bf16 mma.sync flash attention (fp8 output) ================
#define KSTR 72
#define SC2 (0.125f * 1.44269504f)

__global__ __launch_bounds__(128)
void attn_mma_kernel(const bf16* __restrict__ Q, const bf16* __restrict__ K,
                     const bf16* __restrict__ V, fp8* __restrict__ O) {
    __shared__ bf16 Qs[64][KSTR];
    __shared__ bf16 Ks[2][64][KSTR];
    __shared__ bf16 Vs[2][64][KSTR];

    int qt = gridDim.x - 1 - blockIdx.x;
    int h = blockIdx.y, b = blockIdx.z;
    int tid = threadIdx.x;
    int lane = tid & 31, w = tid >> 5;
    size_t headoff = (size_t)h * DHH;

    const bf16* Qbase = Q + ((size_t)(b * SS + qt * 64)) * DD + headoff;
    const bf16* Kbase = K + ((size_t)b * SS) * DD + headoff;
    const bf16* Vbase = V + ((size_t)b * SS) * DD + headoff;

    #pragma unroll
    for (int i = 0; i < 4; i++) {
        int c = tid + i * 128;
        int row = c >> 3, off = (c & 7) * 8;
        cp16(smem_u32(&Qs[row][off]), Qbase + (size_t)row * DD + off);
    }
    cp_commit();
    #pragma unroll
    for (int i = 0; i < 4; i++) {
        int c = tid + i * 128;
        int row = c >> 3, off = (c & 7) * 8;
        cp16(smem_u32(&Ks[0][row][off]), Kbase + (size_t)row * DD + off);
        cp16(smem_u32(&Vs[0][row][off]), Vbase + (size_t)row * DD + off);
    }
    cp_commit();

    cp_wait<1>();
    __syncthreads();
    uint32_t aq[4][4];
    #pragma unroll
    for (int kc = 0; kc < 4; kc++) {
        int row = w * 16 + (lane & 15);
        int col = kc * 16 + (lane >> 4) * 8;
        ldsm_x4(aq[kc][0], aq[kc][1], aq[kc][2], aq[kc][3], smem_u32(&Qs[row][col]));
    }

    float acc_o[8][4];
    #pragma unroll
    for (int nt = 0; nt < 8; nt++)
        #pragma unroll
        for (int v = 0; v < 4; v++) acc_o[nt][v] = 0.f;
    float m[2] = {-INFINITY, -INFINITY};
    float l[2] = {0.f, 0.f};

    int ntiles = qt + 1;
    for (int j = 0; j < ntiles; j++) {
        int st = j & 1;
        if (j + 1 < ntiles) {
            const bf16* kb = Kbase + (size_t)(j + 1) * 64 * DD;
            const bf16* vb = Vbase + (size_t)(j + 1) * 64 * DD;
            #pragma unroll
            for (int i = 0; i < 4; i++) {
                int c = tid + i * 128;
                int row = c >> 3, off = (c & 7) * 8;
                cp16(smem_u32(&Ks[st ^ 1][row][off]), kb + (size_t)row * DD + off);
                cp16(smem_u32(&Vs[st ^ 1][row][off]), vb + (size_t)row * DD + off);
            }
            cp_commit();
            cp_wait<1>();
        } else {
            cp_wait<0>();
        }
        __syncthreads();

        float s[8][4];
        #pragma unroll
        for (int nt = 0; nt < 8; nt++)
            #pragma unroll
            for (int v = 0; v < 4; v++) s[nt][v] = 0.f;
        #pragma unroll
        for (int kc = 0; kc < 4; kc++) {
            uint32_t bk[8][2];
            #pragma unroll
            for (int np = 0; np < 4; np++) {
                int row = np * 16 + (lane & 7) + ((lane & 16) ? 8 : 0);
                int colk = kc * 16 + ((lane & 8) ? 8 : 0);
                uint32_t r0, r1, r2, r3;
                ldsm_x4(r0, r1, r2, r3, smem_u32(&Ks[st][row][colk]));
                bk[np*2][0] = r0; bk[np*2][1] = r1;
                bk[np*2+1][0] = r2; bk[np*2+1][1] = r3;
            }
            #pragma unroll
            for (int nt = 0; nt < 8; nt++)
                mma16816(s[nt], aq[kc], bk[nt]);
        }

        if (j == qt) {
            int r0 = w * 16 + (lane >> 2);
            int cb = (lane & 3) * 2;
            #pragma unroll
            for (int nt = 0; nt < 8; nt++) {
                #pragma unroll
                for (int v = 0; v < 4; v++) {
                    int col = nt * 8 + cb + (v & 1);
                    int row = r0 + ((v & 2) ? 8 : 0);
                    if (col > row) s[nt][v] = -INFINITY;
                }
            }
        }

        #pragma unroll
        for (int rh = 0; rh < 2; rh++) {
            float mt = -INFINITY;
            #pragma unroll
            for (int nt = 0; nt < 8; nt++)
                mt = fmaxf(mt, fmaxf(s[nt][rh*2], s[nt][rh*2+1]));
            mt = fmaxf(mt, __shfl_xor_sync(0xffffffffu, mt, 1));
            mt = fmaxf(mt, __shfl_xor_sync(0xffffffffu, mt, 2));
            float mn = fmaxf(m[rh], mt);
            float corr = exp2f((m[rh] - mn) * SC2);
            m[rh] = mn;
            float ls = 0.f;
            #pragma unroll
            for (int nt = 0; nt < 8; nt++) {
                float p0 = exp2f((s[nt][rh*2]   - mn) * SC2);
                float p1 = exp2f((s[nt][rh*2+1] - mn) * SC2);
                s[nt][rh*2] = p0; s[nt][rh*2+1] = p1;
                ls += p0 + p1;
            }
            ls += __shfl_xor_sync(0xffffffffu, ls, 1);
            ls += __shfl_xor_sync(0xffffffffu, ls, 2);
            l[rh] = l[rh] * corr + ls;
            #pragma unroll
            for (int nt = 0; nt < 8; nt++) {
                acc_o[nt][rh*2]   *= corr;
                acc_o[nt][rh*2+1] *= corr;
            }
        }

        #pragma unroll
        for (int kc = 0; kc < 4; kc++) {
            uint32_t pa[4];
            pa[0] = pack_bf16(s[2*kc][0],   s[2*kc][1]);
            pa[1] = pack_bf16(s[2*kc][2],   s[2*kc][3]);
            pa[2] = pack_bf16(s[2*kc+1][0], s[2*kc+1][1]);
            pa[3] = pack_bf16(s[2*kc+1][2], s[2*kc+1][3]);
            uint32_t bv[8][2];
            #pragma unroll
            for (int np = 0; np < 4; np++) {
                int kr = kc * 16 + (lane & 7) + ((lane & 16) ? 8 : 0);
                int col = np * 16 + ((lane & 8) ? 8 : 0);
                uint32_t r0, r1, r2, r3;
                ldsm_x4_t(r0, r1, r2, r3, smem_u32(&Vs[st][kr][col]));
                bv[np*2][0] = r0; bv[np*2+1][0] = r1;
                bv[np*2][1] = r2; bv[np*2+1][1] = r3;
            }
            #pragma unroll
            for (int nt = 0; nt < 8; nt++)
                mma16816(acc_o[nt], pa, bv[nt]);
        }
        __syncthreads();
    }

    float inv0 = SQ_ATTN / l[0];
    float inv1 = SQ_ATTN / l[1];
    int row0 = qt * 64 + w * 16 + (lane >> 2);
    fp8* Ob = O + ((size_t)b * SS) * DD + headoff;
    #pragma unroll
    for (int nt = 0; nt < 8; nt++) {
        int col = nt * 8 + (lane & 3) * 2;
        *(uint16_t*)(Ob + (size_t)row0 * DD + col)       = pack_fp8x2(acc_o[nt][0] * inv0, acc_o[nt][1] * inv0);
        *(uint16_t*)(Ob + (size_t)(row0 + 8) * DD + col) = pack_fp8x2(acc_o[nt][2] * inv1, acc_o[nt][3] * inv1);
    }
}

// ---------------- launch -----------------------------------------------------
extern "C" void kernel_launch(void* const* d_in, const int* in_sizes, int n_in,
                              void* d_out, int out_size) {
    const float* x       = (const float*)d_in[0];
    const float* f_qk    = (const float*)d_in[1];
    const float* f_v     = (const float*)d_in[2];
    const float* r_qk    = (const float*)d_in[3];
    const float* r_v     = (const float*)d_in[4];
    const float* f_know  = (const float*)d_in[5];
    const float* r_know  = (const float*)d_in[6];
    const float* W_O     = (const float*)d_in[7];
    const float* gamma1  = (const float*)d_in[8];
    const float* beta1   = (const float*)d_in[9];
    const float* gamma2  = (const float*)d_in[10];
    const float* beta2   = (const float*)d_in[11];
    const float* w_fq    = (const float*)d_in[12];
    const float* w_fk    = (const float*)d_in[13];
    const float* w_fv    = (const float*)d_in[14];
    const float* w_rq    = (const float*)d_in[15];
    const float* w_rk    = (const float*)d_in[16];
    const float* w_rv    = (const float*)d_in[17];
    const float* w_know_f= (const float*)d_in[18];
    const float* w_know_r= (const float*)d_in[19];
    float* out = (float*)d_out;

    fp8 *BqkvT, *BknT, *WOb, *rqkT, *rvT, *rknT, *nx, *Tqk, *Tv, *Tkn, *attn;
    bf16 *QKb, *Vb, *allh;
    float *x1;
    cudaGetSymbolAddress((void**)&BqkvT, g_BqkvT);
    cudaGetSymbolAddress((void**)&BknT, g_BknT);
    cudaGetSymbolAddress((void**)&WOb, g_WOb);
    cudaGetSymbolAddress((void**)&rqkT, g_rqkT);
    cudaGetSymbolAddress((void**)&rvT,  g_rvT);
    cudaGetSymbolAddress((void**)&rknT, g_rknT);
    cudaGetSymbolAddress((void**)&nx,  g_nx);
    cudaGetSymbolAddress((void**)&allh, g_allh);
    cudaGetSymbolAddress((void**)&Tqk, g_Tqk);
    cudaGetSymbolAddress((void**)&Tv,  g_Tv);
    cudaGetSymbolAddress((void**)&Tkn, g_Tkn);
    cudaGetSymbolAddress((void**)&QKb, g_QKb);
    cudaGetSymbolAddress((void**)&Vb,  g_Vb);
    cudaGetSymbolAddress((void**)&attn, g_attn);
    cudaGetSymbolAddress((void**)&x1, g_x1);

    // operand prep (batched)
    pack_fT3_kernel<<<dim3((DD*NN*RKK + 255)/256, 1, 3), 256>>>(f_qk, f_v, f_know, BqkvT, BknT);
    cvt_fp8_kernel<<<(DD*DD + 255)/256, 256>>>(W_O, WOb, DD*DD);
    transpose_q3_kernel<<<dim3(DD/32, NRK/32, 3), dim3(32,8)>>>(r_qk, r_v, r_know, rqkT, rvT, rknT);

    // --- attention circuit ---
    ln_kernel<<<BSZ, 256>>>(x, gamma1, beta1, nx);

    qgemm_kernel<bf16><<<dim3(2*NR/128, BSZ/128), 256>>>(nx, BqkvT, allh, nullptr, INV_FEAT, BSZ, 2*NR, DD);

    combineT_kernel<<<BSZ, 256>>>(allh,      2*NR, w_fq, w_fk, w_rq, w_rk, Tqk, Tqk + (size_t)BSZ*NR, RR);
    combineT_kernel<<<BSZ, 256>>>(allh + NR, 2*NR, w_fv, nullptr, w_rv, nullptr, Tv, nullptr, RR);

    qgemm_kernel<bf16><<<dim3(DD/128, 2*BSZ/128), 256>>>(Tqk, rqkT, QKb, nullptr, INV_REST, 2*BSZ, DD, NR);
    qgemm_kernel<bf16><<<dim3(DD/128, BSZ/128), 256>>>(Tv, rvT, Vb, nullptr, INV_REST, BSZ, DD, NR);

    attn_mma_kernel<<<dim3(SS/64, HH, BB), 128>>>(QKb, QKb + (size_t)BSZ*DD, Vb, attn);

    // x1 = x + attn @ W_O^T  (B^T = W_O)
    qgemm_kernel<float><<<dim3(DD/128, BSZ/128), 256>>>(attn, WOb, x1, x, INV_WO, BSZ, DD, DD);

    // --- knowledge circuit ---
    ln_kernel<<<BSZ, 256>>>(x1, gamma2, beta2, nx);
    qgemm_kernel<bf16><<<dim3(NRK/128, BSZ/128), 256>>>(nx, BknT, allh, nullptr, INV_FEAT, BSZ, NRK, DD);
    combineT_kernel<<<BSZ, 256>>>(allh, NRK, w_know_f, nullptr, w_know_r, nullptr, Tkn, nullptr, RKK);
    qgemm_kernel<float><<<dim3(DD/128, BSZ/128), 256>>>(Tkn, rknT, out, x1, INV_REST, BSZ, DD, NRK);
}